// round 2
// baseline (speedup 1.0000x reference)
#include <cuda_runtime.h>

// Problem constants
#define BB   4
#define LL   4096
#define DD   1024
#define MTOT (BB * LL)        // 16384
#define N1   (2 * DD)         // 2048 (GEMM1 N, GEMM2 K)
#define K1   (DD)             // 1024 (GEMM1 K)
#define N2   (DD)             // 1024 (GEMM2 N)

// Scratch: u (post-GEMM1) and xr (post-scan, [real|imag] concat) — 128 MB each.
__device__ float g_u[(size_t)MTOT * N1];
__device__ float g_xr[(size_t)MTOT * N1];

// ---------------------------------------------------------------------------
// Tiled SGEMM: C[m,n] = act( sum_k A[m,k] * Bw[n,k] + bias[n] )
// A: MxK row-major, Bw: NxK row-major (i.e. computes A @ Bw^T)
// 128x128 tile per block, BK=16, 8x8 per thread, 256 threads.
// All dims assumed multiples of tile sizes (true here).
// ---------------------------------------------------------------------------
template<bool RELU>
__device__ __forceinline__ void sgemm_body(const float* __restrict__ A,
                                           const float* __restrict__ Bw,
                                           const float* __restrict__ bias,
                                           float* __restrict__ C,
                                           int M, int N, int K)
{
    // +4 padding: keeps rows 16B-aligned (132*4B = 528B) and reduces the
    // transposed-store conflicts from 4-way to 2-way.
    __shared__ float As[16][132];
    __shared__ float Bs[16][132];

    const int tid   = threadIdx.x;        // 0..255
    const int bm    = blockIdx.y * 128;
    const int bn    = blockIdx.x * 128;
    const int m_sub = (tid >> 4) * 8;     // 0..120
    const int n_sub = (tid & 15) * 8;     // 0..120

    float acc[8][8];
#pragma unroll
    for (int i = 0; i < 8; i++)
#pragma unroll
        for (int j = 0; j < 8; j++) acc[i][j] = 0.0f;

    for (int kt = 0; kt < K; kt += 16) {
        // Load 128x16 tiles of A and Bw (as float4 along k), store k-major.
#pragma unroll
        for (int i = 0; i < 2; i++) {
            int f   = tid + i * 256;      // 0..511 float4 slots
            int row = f >> 2;             // 0..127
            int c4  = (f & 3) * 4;        // 0,4,8,12
            float4 a = *reinterpret_cast<const float4*>(
                A + (size_t)(bm + row) * K + kt + c4);
            As[c4 + 0][row] = a.x;
            As[c4 + 1][row] = a.y;
            As[c4 + 2][row] = a.z;
            As[c4 + 3][row] = a.w;
            float4 b = *reinterpret_cast<const float4*>(
                Bw + (size_t)(bn + row) * K + kt + c4);
            Bs[c4 + 0][row] = b.x;
            Bs[c4 + 1][row] = b.y;
            Bs[c4 + 2][row] = b.z;
            Bs[c4 + 3][row] = b.w;
        }
        __syncthreads();

#pragma unroll
        for (int kk = 0; kk < 16; kk++) {
            float ra[8], rb[8];
#pragma unroll
            for (int i = 0; i < 8; i++) ra[i] = As[kk][m_sub + i];
#pragma unroll
            for (int j = 0; j < 8; j++) rb[j] = Bs[kk][n_sub + j];
#pragma unroll
            for (int i = 0; i < 8; i++)
#pragma unroll
                for (int j = 0; j < 8; j++)
                    acc[i][j] = fmaf(ra[i], rb[j], acc[i][j]);
        }
        __syncthreads();
    }

    // Epilogue: bias (+ReLU), vectorized stores.
#pragma unroll
    for (int i = 0; i < 8; i++) {
        size_t crow = (size_t)(bm + m_sub + i) * N + bn + n_sub;
#pragma unroll
        for (int j = 0; j < 8; j += 4) {
            float4 v;
            v.x = acc[i][j + 0] + bias[bn + n_sub + j + 0];
            v.y = acc[i][j + 1] + bias[bn + n_sub + j + 1];
            v.z = acc[i][j + 2] + bias[bn + n_sub + j + 2];
            v.w = acc[i][j + 3] + bias[bn + n_sub + j + 3];
            if (RELU) {
                v.x = fmaxf(v.x, 0.0f);
                v.y = fmaxf(v.y, 0.0f);
                v.z = fmaxf(v.z, 0.0f);
                v.w = fmaxf(v.w, 0.0f);
            }
            *reinterpret_cast<float4*>(C + crow + j) = v;
        }
    }
}

__global__ __launch_bounds__(256)
void gemm1_kernel(const float* __restrict__ inputs,
                  const float* __restrict__ Wi,
                  const float* __restrict__ bi)
{
    sgemm_body<false>(inputs, Wi, bi, g_u, MTOT, N1, K1);
}

__global__ __launch_bounds__(256)
void gemm2_kernel(const float* __restrict__ Wo,
                  const float* __restrict__ bo,
                  float* __restrict__ out)
{
    sgemm_body<true>(g_xr, Wo, bo, out, MTOT, N2, N1);
}

// ---------------------------------------------------------------------------
// LRU scan: one thread per (b, d) channel.
//   h_t = lambda * h_{t-1} + (u[b,t,2d] + i*u[b,t,2d+1]),  h_{-1} = 0
//   xr[b,t,d]        = gamma_d * Re(h_t)
//   xr[b,t,1024 + d] = gamma_d * Im(h_t)
// lambda = exp(-v_d) * (cos th_d + i sin th_d),  v/th/gamma = exp(params_log)
// ---------------------------------------------------------------------------
__global__ __launch_bounds__(256)
void lru_scan_kernel(const float* __restrict__ params_log)
{
    int idx = blockIdx.x * blockDim.x + threadIdx.x;   // 0..4095
    int d = idx & (DD - 1);
    int b = idx >> 10;

    float v     = expf(params_log[d]);
    float theta = expf(params_log[DD + d]);
    float gamma = expf(params_log[2 * DD + d]);
    float mod   = expf(-v);
    float s, c;
    sincosf(theta, &s, &c);
    float lr = mod * c;
    float li = mod * s;

    const float* up  = g_u  + (size_t)b * LL * N1 + 2 * d;
    float*       xrp = g_xr + (size_t)b * LL * N1 + d;

    float hr = 0.0f, hi = 0.0f;
    for (int t = 0; t < LL; t++) {
        float u0 = up[0];
        float u1 = up[1];
        float nr = fmaf(lr, hr, fmaf(-li, hi, u0));
        float ni = fmaf(lr, hi, fmaf( li, hr, u1));
        hr = nr;
        hi = ni;
        xrp[0]  = gamma * hr;
        xrp[DD] = gamma * hi;
        up  += N1;
        xrp += N1;
    }
}

// ---------------------------------------------------------------------------
// Inputs (metadata order): inputs, Wi, bi, Wo, bo, params_log
// ---------------------------------------------------------------------------
extern "C" void kernel_launch(void* const* d_in, const int* in_sizes, int n_in,
                              void* d_out, int out_size)
{
    const float* inputs     = (const float*)d_in[0];
    const float* Wi         = (const float*)d_in[1];
    const float* bi         = (const float*)d_in[2];
    const float* Wo         = (const float*)d_in[3];
    const float* bo         = (const float*)d_in[4];
    const float* params_log = (const float*)d_in[5];
    float* out = (float*)d_out;

    (void)in_sizes; (void)n_in; (void)out_size;

    // GEMM1: u = inputs @ Wi^T + bi   -> g_u [16384 x 2048]
    {
        dim3 grid(N1 / 128, MTOT / 128);   // 16 x 128
        gemm1_kernel<<<grid, 256>>>(inputs, Wi, bi);
    }
    // Scan: g_u -> g_xr (real|imag concat, scaled by gamma)
    {
        lru_scan_kernel<<<(BB * DD) / 256, 256>>>(params_log);
    }
    // GEMM2: out = relu(g_xr @ Wo^T + bo)  [16384 x 1024]
    {
        dim3 grid(N2 / 128, MTOT / 128);   // 8 x 128
        gemm2_kernel<<<grid, 256>>>(Wo, bo, out);
    }
}

// round 5
// speedup vs baseline: 1.9566x; 1.9566x over previous
#include <cuda_runtime.h>
#include <cuda_bf16.h>
#include <cstdint>

// ---------------------------------------------------------------------------
// Problem constants
// ---------------------------------------------------------------------------
#define BB   4
#define LL   4096
#define DD   1024
#define MTOT (BB * LL)        // 16384
#define N1   (2 * DD)         // 2048
#define K1   (DD)             // 1024
#define N2   (DD)             // 1024

#define CT   64               // scan chunk length
#define NC   (LL / CT)        // 64 chunks
#define NCH  (BB * DD)        // 4096 channels

// ---------------------------------------------------------------------------
// Scratch (device globals; no dynamic allocation allowed)
// ---------------------------------------------------------------------------
__device__ float          g_u[(size_t)MTOT * N1];
__device__ __nv_bfloat16  g_a_hi[(size_t)MTOT * K1];
__device__ __nv_bfloat16  g_a_lo[(size_t)MTOT * K1];
__device__ __nv_bfloat16  g_wi_hi[(size_t)N1 * K1];
__device__ __nv_bfloat16  g_wi_lo[(size_t)N1 * K1];
__device__ __nv_bfloat16  g_wo_hi[(size_t)N2 * N1];
__device__ __nv_bfloat16  g_wo_lo[(size_t)N2 * N1];
__device__ __nv_bfloat16  g_xr_hi[(size_t)MTOT * N1];
__device__ __nv_bfloat16  g_xr_lo[(size_t)MTOT * N1];
__device__ float2         g_F[NC * NCH];
__device__ float2         g_carry[NC * NCH];

// ---------------------------------------------------------------------------
// PTX helpers (base compute_103 only — NO arch-'a' features)
// ---------------------------------------------------------------------------
__device__ __forceinline__ uint32_t smem_u32(const void* p) {
    uint32_t a;
    asm("{ .reg .u64 t; cvta.to.shared.u64 t, %1; cvt.u32.u64 %0, t; }"
        : "=r"(a) : "l"(p));
    return a;
}
__device__ __forceinline__ void cp_async16(uint32_t dst, const void* src) {
    asm volatile("cp.async.cg.shared.global [%0], [%1], 16;"
                 :: "r"(dst), "l"(src));
}
__device__ __forceinline__ void cp_commit() {
    asm volatile("cp.async.commit_group;");
}
template<int N>
__device__ __forceinline__ void cp_wait() {
    asm volatile("cp.async.wait_group %0;" :: "n"(N));
}
__device__ __forceinline__ void ldmatrix_x4(uint32_t* r, uint32_t addr) {
    asm volatile("ldmatrix.sync.aligned.m8n8.x4.shared.b16 {%0,%1,%2,%3}, [%4];"
                 : "=r"(r[0]), "=r"(r[1]), "=r"(r[2]), "=r"(r[3]) : "r"(addr));
}
__device__ __forceinline__ void mma16816(float* d, const uint32_t* a,
                                         uint32_t b0, uint32_t b1) {
    asm volatile(
        "mma.sync.aligned.m16n8k16.row.col.f32.bf16.bf16.f32 "
        "{%0,%1,%2,%3}, {%4,%5,%6,%7}, {%8,%9}, {%0,%1,%2,%3};"
        : "+f"(d[0]), "+f"(d[1]), "+f"(d[2]), "+f"(d[3])
        : "r"(a[0]), "r"(a[1]), "r"(a[2]), "r"(a[3]), "r"(b0), "r"(b1));
}

// ---------------------------------------------------------------------------
// bf16-split mma.sync GEMM:
//   C[m,n] = act( sum_k (Ah+Al)[m,k]*(Bh+Bl)[n,k] + bias[n] )   (AlBl dropped)
// CTA tile 128x128, BK=32, 3-stage cp.async pipeline, 8 warps (2M x 4N),
// warp tile 64x32. Smem rows padded to 80B (5 chunks, coprime 8 -> no
// ldmatrix bank conflicts).
// ---------------------------------------------------------------------------
#define BM      128
#define BN      128
#define BK      32
#define STAGES  3
#define ROWB    80                       // bytes per smem row (64 data + 16 pad)
#define TILEB   (128 * ROWB)             // 10240 B
#define STAGEB  (4 * TILEB)              // Ah, Al, Bh, Bl
#define GSMEM   (STAGES * STAGEB)        // 122880 B

template<bool RELU>
__global__ __launch_bounds__(256)
void gemm_mma_kernel(const __nv_bfloat16* __restrict__ Ah,
                     const __nv_bfloat16* __restrict__ Al,
                     const __nv_bfloat16* __restrict__ Bh,
                     const __nv_bfloat16* __restrict__ Bl,
                     const float* __restrict__ bias,
                     float* __restrict__ C,
                     int N, int K)
{
    extern __shared__ __align__(128) char smem[];
    const uint32_t sbase = smem_u32(smem);

    const int tid    = threadIdx.x;
    const int lane   = tid & 31;
    const int wid    = tid >> 5;
    const int warp_m = wid & 1;          // 0..1 -> 64-row half
    const int warp_n = wid >> 1;         // 0..3 -> 32-col quarter
    const int bn     = blockIdx.x * BN;
    const int bm     = blockIdx.y * BM;

    // ---- cp.async stage loader: 2048 16B chunks / 256 threads = 8 each ----
    // chunk id g: tile = g>>9 (0:Ah 1:Al 2:Bh 3:Bl), row = (g>>2)&127, kc = g&3
    auto load_stage = [&](int stage, int kt) {
        const uint32_t sb = sbase + stage * STAGEB;
#pragma unroll
        for (int j = 0; j < 8; j++) {
            int g    = tid + j * 256;
            int tile = g >> 9;
            int row  = (g >> 2) & 127;
            int kc   = g & 3;
            uint32_t daddr = sb + tile * TILEB + row * ROWB + kc * 16;
            const __nv_bfloat16* src;
            if (tile == 0)      src = Ah + (size_t)(bm + row) * K + kt + kc * 8;
            else if (tile == 1) src = Al + (size_t)(bm + row) * K + kt + kc * 8;
            else if (tile == 2) src = Bh + (size_t)(bn + row) * K + kt + kc * 8;
            else                src = Bl + (size_t)(bn + row) * K + kt + kc * 8;
            cp_async16(daddr, src);
        }
    };

    float acc[4][4][4];                  // [mt][nt][frag]
#pragma unroll
    for (int i = 0; i < 4; i++)
#pragma unroll
        for (int j = 0; j < 4; j++)
#pragma unroll
            for (int f = 0; f < 4; f++) acc[i][j][f] = 0.0f;

    const int niter = K / BK;

    // Prologue: fill stages 0..STAGES-2
    load_stage(0, 0);  cp_commit();
    load_stage(1, BK); cp_commit();

    // Per-lane ldmatrix row bases (row-within-tile = l%16, chunk = l/16)
    const uint32_t lrow = (lane & 15) * ROWB + (lane >> 4) * 16;
    const uint32_t a_off = (warp_m * 64) * ROWB + lrow;      // + mt*16*ROWB + ks*32
    const uint32_t b_off = (warp_n * 32) * ROWB + lrow;      // + nt16*16*ROWB + ks*32

    for (int it = 0; it < niter; it++) {
        cp_wait<1>();
        __syncthreads();

        if (it + 2 < niter) load_stage((it + 2) % STAGES, (it + 2) * BK);
        cp_commit();

        const uint32_t sb  = sbase + (it % STAGES) * STAGEB;
        const uint32_t sAh = sb + 0 * TILEB + a_off;
        const uint32_t sAl = sb + 1 * TILEB + a_off;
        const uint32_t sBh = sb + 2 * TILEB + b_off;
        const uint32_t sBl = sb + 3 * TILEB + b_off;

#pragma unroll
        for (int ks = 0; ks < 2; ks++) {
            const uint32_t ko = ks * 32;          // 16 bf16 = 32 bytes
            uint32_t ah[4][4], al[4][4];
#pragma unroll
            for (int mt = 0; mt < 4; mt++) {
                ldmatrix_x4(ah[mt], sAh + mt * (16 * ROWB) + ko);
                ldmatrix_x4(al[mt], sAl + mt * (16 * ROWB) + ko);
            }
            // B: two 16-row ldmatrix.x4 per operand cover n0..31
            uint32_t bh[2][4], bl[2][4];
#pragma unroll
            for (int ng = 0; ng < 2; ng++) {
                ldmatrix_x4(bh[ng], sBh + ng * (16 * ROWB) + ko);
                ldmatrix_x4(bl[ng], sBl + ng * (16 * ROWB) + ko);
            }
#pragma unroll
            for (int nt = 0; nt < 4; nt++) {
                const int ng = nt >> 1, nh = nt & 1;
                const uint32_t bh0 = bh[ng][nh], bh1 = bh[ng][nh + 2];
                const uint32_t bl0 = bl[ng][nh], bl1 = bl[ng][nh + 2];
#pragma unroll
                for (int mt = 0; mt < 4; mt++) {
                    mma16816(acc[mt][nt], ah[mt], bh0, bh1);
                    mma16816(acc[mt][nt], ah[mt], bl0, bl1);
                    mma16816(acc[mt][nt], al[mt], bh0, bh1);
                }
            }
        }
    }

    // ---- Epilogue: bias (+ReLU), store fp32 ----
    const int mrow0 = bm + warp_m * 64 + (lane >> 2);
    const int ncol0 = bn + warp_n * 32 + 2 * (lane & 3);
#pragma unroll
    for (int mt = 0; mt < 4; mt++) {
#pragma unroll
        for (int nt = 0; nt < 4; nt++) {
            const int n = ncol0 + nt * 8;
            const float b0 = bias[n], b1 = bias[n + 1];
            float2 v0, v1;
            v0.x = acc[mt][nt][0] + b0;  v0.y = acc[mt][nt][1] + b1;
            v1.x = acc[mt][nt][2] + b0;  v1.y = acc[mt][nt][3] + b1;
            if (RELU) {
                v0.x = fmaxf(v0.x, 0.0f); v0.y = fmaxf(v0.y, 0.0f);
                v1.x = fmaxf(v1.x, 0.0f); v1.y = fmaxf(v1.y, 0.0f);
            }
            const int m = mrow0 + mt * 16;
            *(float2*)(C + (size_t)m * N + n)       = v0;
            *(float2*)(C + (size_t)(m + 8) * N + n) = v1;
        }
    }
}

// ---------------------------------------------------------------------------
// fp32 -> bf16 hi/lo split (vectorized by 4)
// ---------------------------------------------------------------------------
__global__ __launch_bounds__(256)
void split_kernel(const float* __restrict__ src,
                  __nv_bfloat16* __restrict__ hi,
                  __nv_bfloat16* __restrict__ lo, int n4)
{
    int i = blockIdx.x * blockDim.x + threadIdx.x;
    if (i >= n4) return;
    float4 x = ((const float4*)src)[i];
    __nv_bfloat16 h0 = __float2bfloat16_rn(x.x);
    __nv_bfloat16 h1 = __float2bfloat16_rn(x.y);
    __nv_bfloat16 h2 = __float2bfloat16_rn(x.z);
    __nv_bfloat16 h3 = __float2bfloat16_rn(x.w);
    __nv_bfloat162* hp = (__nv_bfloat162*)hi;
    __nv_bfloat162* lp = (__nv_bfloat162*)lo;
    hp[2 * i + 0] = __nv_bfloat162(h0, h1);
    hp[2 * i + 1] = __nv_bfloat162(h2, h3);
    lp[2 * i + 0] = __nv_bfloat162(
        __float2bfloat16_rn(x.x - __bfloat162float(h0)),
        __float2bfloat16_rn(x.y - __bfloat162float(h1)));
    lp[2 * i + 1] = __nv_bfloat162(
        __float2bfloat16_rn(x.z - __bfloat162float(h2)),
        __float2bfloat16_rn(x.w - __bfloat162float(h3)));
}

// ---------------------------------------------------------------------------
// Chunked LRU scan (3 passes)
// ---------------------------------------------------------------------------
__global__ __launch_bounds__(256)
void scan_pass1(const float* __restrict__ params_log)
{
    int idx = blockIdx.x * blockDim.x + threadIdx.x;
    int ch  = idx & (NCH - 1);
    int c   = idx >> 12;
    int d   = ch & (DD - 1);
    int b   = ch >> 10;

    float v  = expf(params_log[d]);
    float th = expf(params_log[DD + d]);
    float mod = expf(-v);
    float s, co; sincosf(th, &s, &co);
    float lr = mod * co, li = mod * s;

    const float* up = g_u + ((size_t)(b * LL + c * CT)) * N1 + 2 * d;
    float hr = 0.0f, hi = 0.0f;
#pragma unroll 4
    for (int t = 0; t < CT; t++) {
        float u0 = up[0], u1 = up[1];
        float nr = fmaf(lr, hr, fmaf(-li, hi, u0));
        float ni = fmaf(lr, hi, fmaf( li, hr, u1));
        hr = nr; hi = ni;
        up += N1;
    }
    g_F[idx] = make_float2(hr, hi);
}

__global__ __launch_bounds__(256)
void scan_combine(const float* __restrict__ params_log)
{
    int ch = blockIdx.x * blockDim.x + threadIdx.x;
    int d  = ch & (DD - 1);

    double v  = exp((double)params_log[d]);
    double th = exp((double)params_log[DD + d]);
    double modT = exp(-(double)CT * v);
    double ang  = (double)CT * th;
    double lTr = modT * cos(ang), lTi = modT * sin(ang);

    double Sr = 0.0, Si = 0.0;
    for (int c = 0; c < NC; c++) {
        g_carry[c * NCH + ch] = make_float2((float)Sr, (float)Si);
        float2 F = g_F[c * NCH + ch];
        double nr = lTr * Sr - lTi * Si + (double)F.x;
        double ni = lTr * Si + lTi * Sr + (double)F.y;
        Sr = nr; Si = ni;
    }
}

__global__ __launch_bounds__(256)
void scan_pass2(const float* __restrict__ params_log)
{
    int idx = blockIdx.x * blockDim.x + threadIdx.x;
    int ch  = idx & (NCH - 1);
    int c   = idx >> 12;
    int d   = ch & (DD - 1);
    int b   = ch >> 10;

    float v  = expf(params_log[d]);
    float th = expf(params_log[DD + d]);
    float gamma = expf(params_log[2 * DD + d]);
    float mod = expf(-v);
    float s, co; sincosf(th, &s, &co);
    float lr = mod * co, li = mod * s;

    float2 cr = g_carry[c * NCH + ch];
    float hr = cr.x, hi = cr.y;

    const float* up = g_u + ((size_t)(b * LL + c * CT)) * N1 + 2 * d;
    size_t o = ((size_t)(b * LL + c * CT)) * N1 + d;
#pragma unroll 2
    for (int t = 0; t < CT; t++) {
        float u0 = up[0], u1 = up[1];
        float nr = fmaf(lr, hr, fmaf(-li, hi, u0));
        float ni = fmaf(lr, hi, fmaf( li, hr, u1));
        hr = nr; hi = ni;
        float xr = gamma * hr, xi = gamma * hi;
        __nv_bfloat16 xh = __float2bfloat16_rn(xr);
        __nv_bfloat16 ih = __float2bfloat16_rn(xi);
        g_xr_hi[o]      = xh;
        g_xr_lo[o]      = __float2bfloat16_rn(xr - __bfloat162float(xh));
        g_xr_hi[o + DD] = ih;
        g_xr_lo[o + DD] = __float2bfloat16_rn(xi - __bfloat162float(ih));
        up += N1;
        o  += N1;
    }
}

// ---------------------------------------------------------------------------
// Inputs: inputs, Wi, bi, Wo, bo, params_log
// ---------------------------------------------------------------------------
extern "C" void kernel_launch(void* const* d_in, const int* in_sizes, int n_in,
                              void* d_out, int out_size)
{
    const float* inputs     = (const float*)d_in[0];
    const float* Wi         = (const float*)d_in[1];
    const float* bi         = (const float*)d_in[2];
    const float* Wo         = (const float*)d_in[3];
    const float* bo         = (const float*)d_in[4];
    const float* params_log = (const float*)d_in[5];
    float* out = (float*)d_out;
    (void)in_sizes; (void)n_in; (void)out_size;

    static bool attr_done = false;
    if (!attr_done) {
        cudaFuncSetAttribute(gemm_mma_kernel<false>,
                             cudaFuncAttributeMaxDynamicSharedMemorySize, GSMEM);
        cudaFuncSetAttribute(gemm_mma_kernel<true>,
                             cudaFuncAttributeMaxDynamicSharedMemorySize, GSMEM);
        attr_done = true;
    }

    __nv_bfloat16 *a_hi, *a_lo, *wi_hi, *wi_lo, *wo_hi, *wo_lo, *xr_hi, *xr_lo;
    float* u;
    cudaGetSymbolAddress((void**)&a_hi,  g_a_hi);
    cudaGetSymbolAddress((void**)&a_lo,  g_a_lo);
    cudaGetSymbolAddress((void**)&wi_hi, g_wi_hi);
    cudaGetSymbolAddress((void**)&wi_lo, g_wi_lo);
    cudaGetSymbolAddress((void**)&wo_hi, g_wo_hi);
    cudaGetSymbolAddress((void**)&wo_lo, g_wo_lo);
    cudaGetSymbolAddress((void**)&xr_hi, g_xr_hi);
    cudaGetSymbolAddress((void**)&xr_lo, g_xr_lo);
    cudaGetSymbolAddress((void**)&u,     g_u);

    // Splits
    {
        int n4 = (MTOT * K1) / 4;
        split_kernel<<<(n4 + 255) / 256, 256>>>(inputs, a_hi, a_lo, n4);
    }
    {
        int n4 = (N1 * K1) / 4;
        split_kernel<<<(n4 + 255) / 256, 256>>>(Wi, wi_hi, wi_lo, n4);
    }
    {
        int n4 = (N2 * N1) / 4;
        split_kernel<<<(n4 + 255) / 256, 256>>>(Wo, wo_hi, wo_lo, n4);
    }

    // GEMM1: u = inputs @ Wi^T + bi  -> g_u [16384 x 2048] fp32
    {
        dim3 grid(N1 / BN, MTOT / BM);
        gemm_mma_kernel<false><<<grid, 256, GSMEM>>>(
            a_hi, a_lo, wi_hi, wi_lo, bi, u, N1, K1);
    }

    // Scan
    scan_pass1 <<<(NCH * NC) / 256, 256>>>(params_log);
    scan_combine<<<NCH / 256, 256>>>(params_log);
    scan_pass2 <<<(NCH * NC) / 256, 256>>>(params_log);

    // GEMM2: out = relu(xr @ Wo^T + bo)  [16384 x 1024]
    {
        dim3 grid(N2 / BN, MTOT / BM);
        gemm_mma_kernel<true><<<grid, 256, GSMEM>>>(
            xr_hi, xr_lo, wo_hi, wo_lo, bo, out, N2, N1);
    }
}

// round 7
// speedup vs baseline: 5.4173x; 2.7687x over previous
#include <cuda_runtime.h>
#include <cuda_fp16.h>
#include <cstdint>

// ---------------------------------------------------------------------------
// Problem constants
// ---------------------------------------------------------------------------
#define BB   4
#define LL   4096
#define DD   1024
#define MTOT (BB * LL)        // 16384
#define N1   (2 * DD)         // 2048
#define K1   (DD)             // 1024
#define N2   (DD)             // 1024

#define CT   64               // scan chunk length
#define NC   (LL / CT)        // 64 chunks
#define NCH  (BB * DD)        // 4096 channels

// ---------------------------------------------------------------------------
// Scratch (device globals)
// ---------------------------------------------------------------------------
__device__ float   g_u[(size_t)MTOT * N1];        // GEMM1 out (fp32)
__device__ __half  g_a16[(size_t)MTOT * K1];      // inputs as fp16
__device__ __half  g_wi_h[(size_t)N1 * K1];       // Wi split hi/lo fp16
__device__ __half  g_wi_l[(size_t)N1 * K1];
__device__ __half  g_wo_h[(size_t)N2 * N1];       // Wo split hi/lo fp16
__device__ __half  g_wo_l[(size_t)N2 * N1];
__device__ __half  g_xr16[(size_t)MTOT * N1];     // scan out as fp16
__device__ float2  g_F[NC * NCH];
__device__ float2  g_carry[NC * NCH];

// ---------------------------------------------------------------------------
// PTX helpers (base compute_103 only)
// ---------------------------------------------------------------------------
__device__ __forceinline__ uint32_t smem_u32(const void* p) {
    uint32_t a;
    asm("{ .reg .u64 t; cvta.to.shared.u64 t, %1; cvt.u32.u64 %0, t; }"
        : "=r"(a) : "l"(p));
    return a;
}
__device__ __forceinline__ void cp_async16(uint32_t dst, const void* src) {
    asm volatile("cp.async.cg.shared.global [%0], [%1], 16;"
                 :: "r"(dst), "l"(src));
}
__device__ __forceinline__ void cp_commit() {
    asm volatile("cp.async.commit_group;");
}
template<int N>
__device__ __forceinline__ void cp_wait() {
    asm volatile("cp.async.wait_group %0;" :: "n"(N));
}
__device__ __forceinline__ void ldmatrix_x4(uint32_t* r, uint32_t addr) {
    asm volatile("ldmatrix.sync.aligned.m8n8.x4.shared.b16 {%0,%1,%2,%3}, [%4];"
                 : "=r"(r[0]), "=r"(r[1]), "=r"(r[2]), "=r"(r[3]) : "r"(addr));
}
__device__ __forceinline__ void mma16816(float* d, const uint32_t* a,
                                         uint32_t b0, uint32_t b1) {
    asm volatile(
        "mma.sync.aligned.m16n8k16.row.col.f32.f16.f16.f32 "
        "{%0,%1,%2,%3}, {%4,%5,%6,%7}, {%8,%9}, {%0,%1,%2,%3};"
        : "+f"(d[0]), "+f"(d[1]), "+f"(d[2]), "+f"(d[3])
        : "r"(a[0]), "r"(a[1]), "r"(a[2]), "r"(a[3]), "r"(b0), "r"(b1));
}

// ---------------------------------------------------------------------------
// 2-term fp16 GEMM:  C[m,n] = act( sum_k A16[m,k]*(Wh+Wl)[n,k] + bias[n] )
// CTA tile 128x128, BK=32, 4-stage cp.async pipeline, 8 warps (2M x 4N),
// warp tile 64x32. SW64 swizzle (no padding): chunk col c' = c ^ ((row>>1)&3).
// smem = 4 stages * 3 tiles * 8192B = 96 KB  ->  2 CTAs/SM.
// ---------------------------------------------------------------------------
#define BM      128
#define BN      128
#define BK      32
#define STAGES  4
#define TILEB   (128 * 64)               // 8192 B (128 rows x 64 B)
#define STAGEB  (3 * TILEB)              // A, Wh, Wl
#define GSMEM   (STAGES * STAGEB)        // 98304 B

template<bool RELU>
__global__ __launch_bounds__(256, 2)
void gemm_mma_kernel(const __half* __restrict__ A,
                     const __half* __restrict__ Bh,
                     const __half* __restrict__ Bl,
                     const float* __restrict__ bias,
                     float* __restrict__ C,
                     int N, int K)
{
    extern __shared__ __align__(128) char smem[];
    const uint32_t sbase = smem_u32(smem);

    const int tid    = threadIdx.x;
    const int lane   = tid & 31;
    const int wid    = tid >> 5;
    const int warp_m = wid & 1;          // 64-row half
    const int warp_n = wid >> 1;         // 32-col quarter
    const int bn     = blockIdx.x * BN;
    const int bm     = blockIdx.y * BM;

    // Stage loader: 1536 16B chunks / 256 threads = 6 each.
    // g: tile = g>>9 (0:A 1:Bh 2:Bl), row = (g>>2)&127, kc = g&3
    auto load_stage = [&](int stage, int kt) {
        const uint32_t sb = sbase + stage * STAGEB;
#pragma unroll
        for (int j = 0; j < 6; j++) {
            int g    = tid + j * 256;
            int tile = g >> 9;
            int row  = (g >> 2) & 127;
            int kc   = g & 3;
            uint32_t d = sb + tile * TILEB + row * 64
                       + ((kc * 16) ^ (((row >> 1) & 3) << 4));
            const __half* src;
            if (tile == 0)      src = A  + (size_t)(bm + row) * K + kt + kc * 8;
            else if (tile == 1) src = Bh + (size_t)(bn + row) * K + kt + kc * 8;
            else                src = Bl + (size_t)(bn + row) * K + kt + kc * 8;
            cp_async16(d, src);
        }
    };

    float acc[4][4][4];
#pragma unroll
    for (int i = 0; i < 4; i++)
#pragma unroll
        for (int j = 0; j < 4; j++)
#pragma unroll
            for (int f = 0; f < 4; f++) acc[i][j][f] = 0.0f;

    const int niter = K / BK;

    // Prologue: fill 3 stages
    load_stage(0, 0);      cp_commit();
    load_stage(1, BK);     cp_commit();
    load_stage(2, 2 * BK); cp_commit();

    // Per-lane ldmatrix addressing (swizzle term depends only on row bits 1-2)
    const uint32_t swz  = (uint32_t)(((lane >> 1) & 3) << 4);
    const uint32_t colh = (uint32_t)((lane >> 4) * 16);
    const uint32_t aoff = (uint32_t)((warp_m * 64 + (lane & 15)) * 64);
    const uint32_t boff = (uint32_t)((warp_n * 32 + (lane & 15)) * 64);

    for (int it = 0; it < niter; it++) {
        cp_wait<2>();
        __syncthreads();

        if (it + 3 < niter) load_stage((it + 3) & 3, (it + 3) * BK);
        cp_commit();

        const uint32_t sb = sbase + (it & 3) * STAGEB;
#pragma unroll
        for (int ks = 0; ks < 2; ks++) {
            const uint32_t cofs = ((uint32_t)(ks * 32) + colh) ^ swz;
            uint32_t a[4][4];
#pragma unroll
            for (int mt = 0; mt < 4; mt++)
                ldmatrix_x4(a[mt], sb + 0 * TILEB + aoff + mt * 1024 + cofs);
            uint32_t bh[2][4], bl[2][4];
#pragma unroll
            for (int ng = 0; ng < 2; ng++) {
                ldmatrix_x4(bh[ng], sb + 1 * TILEB + boff + ng * 1024 + cofs);
                ldmatrix_x4(bl[ng], sb + 2 * TILEB + boff + ng * 1024 + cofs);
            }
#pragma unroll
            for (int nt = 0; nt < 4; nt++) {
                const int ng = nt >> 1, nh = nt & 1;
                const uint32_t h0 = bh[ng][nh], h1 = bh[ng][nh + 2];
                const uint32_t l0 = bl[ng][nh], l1 = bl[ng][nh + 2];
#pragma unroll
                for (int mt = 0; mt < 4; mt++)
                    mma16816(acc[mt][nt], a[mt], h0, h1);
#pragma unroll
                for (int mt = 0; mt < 4; mt++)
                    mma16816(acc[mt][nt], a[mt], l0, l1);
            }
        }
    }

    // Epilogue: bias (+ReLU), fp32 stores
    const int mrow0 = bm + warp_m * 64 + (lane >> 2);
    const int ncol0 = bn + warp_n * 32 + 2 * (lane & 3);
#pragma unroll
    for (int mt = 0; mt < 4; mt++) {
#pragma unroll
        for (int nt = 0; nt < 4; nt++) {
            const int n = ncol0 + nt * 8;
            const float b0 = bias[n], b1 = bias[n + 1];
            float2 v0, v1;
            v0.x = acc[mt][nt][0] + b0;  v0.y = acc[mt][nt][1] + b1;
            v1.x = acc[mt][nt][2] + b0;  v1.y = acc[mt][nt][3] + b1;
            if (RELU) {
                v0.x = fmaxf(v0.x, 0.0f); v0.y = fmaxf(v0.y, 0.0f);
                v1.x = fmaxf(v1.x, 0.0f); v1.y = fmaxf(v1.y, 0.0f);
            }
            const int m = mrow0 + mt * 16;
            *(float2*)(C + (size_t)m * N + n)       = v0;
            *(float2*)(C + (size_t)(m + 8) * N + n) = v1;
        }
    }
}

// ---------------------------------------------------------------------------
// fp32 -> fp16 (activations)
// ---------------------------------------------------------------------------
__global__ __launch_bounds__(256)
void to_half_kernel(const float* __restrict__ src, __half* __restrict__ dst,
                    int n4)
{
    int i = blockIdx.x * blockDim.x + threadIdx.x;
    if (i >= n4) return;
    float4 x = ((const float4*)src)[i];
    __half2* dp = (__half2*)dst;
    dp[2 * i + 0] = __floats2half2_rn(x.x, x.y);
    dp[2 * i + 1] = __floats2half2_rn(x.z, x.w);
}

// fp32 -> fp16 hi/lo (weights)
__global__ __launch_bounds__(256)
void split_w_kernel(const float* __restrict__ src,
                    __half* __restrict__ hi, __half* __restrict__ lo, int n4)
{
    int i = blockIdx.x * blockDim.x + threadIdx.x;
    if (i >= n4) return;
    float4 x = ((const float4*)src)[i];
    __half h0 = __float2half_rn(x.x);
    __half h1 = __float2half_rn(x.y);
    __half h2 = __float2half_rn(x.z);
    __half h3 = __float2half_rn(x.w);
    __half2* hp = (__half2*)hi;
    __half2* lp = (__half2*)lo;
    hp[2 * i + 0] = __half2(h0, h1);
    hp[2 * i + 1] = __half2(h2, h3);
    lp[2 * i + 0] = __half2(__float2half_rn(x.x - __half2float(h0)),
                            __float2half_rn(x.y - __half2float(h1)));
    lp[2 * i + 1] = __half2(__float2half_rn(x.z - __half2float(h2)),
                            __float2half_rn(x.w - __half2float(h3)));
}

// ---------------------------------------------------------------------------
// Chunked LRU scan (3 passes)
// ---------------------------------------------------------------------------
__global__ __launch_bounds__(256)
void scan_pass1(const float* __restrict__ params_log)
{
    int idx = blockIdx.x * blockDim.x + threadIdx.x;
    int ch  = idx & (NCH - 1);
    int c   = idx >> 12;
    int d   = ch & (DD - 1);
    int b   = ch >> 10;

    float v  = expf(params_log[d]);
    float th = expf(params_log[DD + d]);
    float mod = expf(-v);
    float s, co; sincosf(th, &s, &co);
    float lr = mod * co, li = mod * s;

    const float* up = g_u + ((size_t)(b * LL + c * CT)) * N1 + 2 * d;
    float hr = 0.0f, hi = 0.0f;
#pragma unroll 4
    for (int t = 0; t < CT; t++) {
        float u0 = up[0], u1 = up[1];
        float nr = fmaf(lr, hr, fmaf(-li, hi, u0));
        float ni = fmaf(lr, hi, fmaf( li, hr, u1));
        hr = nr; hi = ni;
        up += N1;
    }
    g_F[idx] = make_float2(hr, hi);
}

__global__ __launch_bounds__(256)
void scan_combine(const float* __restrict__ params_log)
{
    int ch = blockIdx.x * blockDim.x + threadIdx.x;
    int d  = ch & (DD - 1);

    double v  = exp((double)params_log[d]);
    double th = exp((double)params_log[DD + d]);
    double modT = exp(-(double)CT * v);
    double ang  = (double)CT * th;
    double lTr = modT * cos(ang), lTi = modT * sin(ang);

    double Sr = 0.0, Si = 0.0;
    for (int c = 0; c < NC; c++) {
        g_carry[c * NCH + ch] = make_float2((float)Sr, (float)Si);
        float2 F = g_F[c * NCH + ch];
        double nr = lTr * Sr - lTi * Si + (double)F.x;
        double ni = lTr * Si + lTi * Sr + (double)F.y;
        Sr = nr; Si = ni;
    }
}

__global__ __launch_bounds__(256)
void scan_pass2(const float* __restrict__ params_log)
{
    int idx = blockIdx.x * blockDim.x + threadIdx.x;
    int ch  = idx & (NCH - 1);
    int c   = idx >> 12;
    int d   = ch & (DD - 1);
    int b   = ch >> 10;

    float v  = expf(params_log[d]);
    float th = expf(params_log[DD + d]);
    float gamma = expf(params_log[2 * DD + d]);
    float mod = expf(-v);
    float s, co; sincosf(th, &s, &co);
    float lr = mod * co, li = mod * s;

    float2 cr = g_carry[c * NCH + ch];
    float hr = cr.x, hi = cr.y;

    const float* up = g_u + ((size_t)(b * LL + c * CT)) * N1 + 2 * d;
    size_t o = ((size_t)(b * LL + c * CT)) * N1 + d;
#pragma unroll 2
    for (int t = 0; t < CT; t++) {
        float u0 = up[0], u1 = up[1];
        float nr = fmaf(lr, hr, fmaf(-li, hi, u0));
        float ni = fmaf(lr, hi, fmaf( li, hr, u1));
        hr = nr; hi = ni;
        g_xr16[o]      = __float2half_rn(gamma * hr);
        g_xr16[o + DD] = __float2half_rn(gamma * hi);
        up += N1;
        o  += N1;
    }
}

// ---------------------------------------------------------------------------
// Inputs: inputs, Wi, bi, Wo, bo, params_log
// ---------------------------------------------------------------------------
extern "C" void kernel_launch(void* const* d_in, const int* in_sizes, int n_in,
                              void* d_out, int out_size)
{
    const float* inputs     = (const float*)d_in[0];
    const float* Wi         = (const float*)d_in[1];
    const float* bi         = (const float*)d_in[2];
    const float* Wo         = (const float*)d_in[3];
    const float* bo         = (const float*)d_in[4];
    const float* params_log = (const float*)d_in[5];
    float* out = (float*)d_out;
    (void)in_sizes; (void)n_in; (void)out_size;

    static bool attr_done = false;
    if (!attr_done) {
        cudaFuncSetAttribute(gemm_mma_kernel<false>,
                             cudaFuncAttributeMaxDynamicSharedMemorySize, GSMEM);
        cudaFuncSetAttribute(gemm_mma_kernel<true>,
                             cudaFuncAttributeMaxDynamicSharedMemorySize, GSMEM);
        attr_done = true;
    }

    __half *a16, *wi_h, *wi_l, *wo_h, *wo_l, *xr16;
    float* u;
    cudaGetSymbolAddress((void**)&a16,  g_a16);
    cudaGetSymbolAddress((void**)&wi_h, g_wi_h);
    cudaGetSymbolAddress((void**)&wi_l, g_wi_l);
    cudaGetSymbolAddress((void**)&wo_h, g_wo_h);
    cudaGetSymbolAddress((void**)&wo_l, g_wo_l);
    cudaGetSymbolAddress((void**)&xr16, g_xr16);
    cudaGetSymbolAddress((void**)&u,    g_u);

    // Conversions
    {
        int n4 = (MTOT * K1) / 4;
        to_half_kernel<<<(n4 + 255) / 256, 256>>>(inputs, a16, n4);
    }
    {
        int n4 = (N1 * K1) / 4;
        split_w_kernel<<<(n4 + 255) / 256, 256>>>(Wi, wi_h, wi_l, n4);
    }
    {
        int n4 = (N2 * N1) / 4;
        split_w_kernel<<<(n4 + 255) / 256, 256>>>(Wo, wo_h, wo_l, n4);
    }

    // GEMM1: u = inputs @ Wi^T + bi
    {
        dim3 grid(N1 / BN, MTOT / BM);
        gemm_mma_kernel<false><<<grid, 256, GSMEM>>>(
            a16, wi_h, wi_l, bi, u, N1, K1);
    }

    // Scan
    scan_pass1 <<<(NCH * NC) / 256, 256>>>(params_log);
    scan_combine<<<NCH / 256, 256>>>(params_log);
    scan_pass2 <<<(NCH * NC) / 256, 256>>>(params_log);

    // GEMM2: out = relu(xr @ Wo^T + bo)
    {
        dim3 grid(N2 / BN, MTOT / BM);
        gemm_mma_kernel<true><<<grid, 256, GSMEM>>>(
            xr16, wo_h, wo_l, bo, out, N2, N1);
    }
}